// round 15
// baseline (speedup 1.0000x reference)
#include <cuda_runtime.h>
#include <cuda_fp16.h>
#include <math.h>
#include <cstdint>

// ---------------------------------------------------------------------------
// KimiDeltaAttention  (B=1, T=1024, DM=2048, H=16, DH=128, KD=2048, KC=4)
// Round 15: recurrence v7 — split-CTA: two independent 128-thread pipelines
// per CTA (named barriers), each with its own 8-stage ring + 8 columns.
// Stall exposure in one half is hidden by the other. Math identical to v6.
// ---------------------------------------------------------------------------

#define T_LEN 1024
#define DM    2048
#define NH    16
#define DH    128
#define KD    2048

static constexpr size_t NTK = (size_t)T_LEN * KD;   // 2097152

// fp32 scratch
#define OFF_QKV  ((size_t)0)
#define OFF_QC   (NTK * 3)
#define OFF_KC   (NTK * 4)
#define OFF_VC   (NTK * 5)
#define OFF_EG   (NTK * 6)
#define OFF_GOUT (NTK * 7)
#define OFF_O    (NTK * 8)
#define OFF_FA   (NTK * 9)
#define OFF_BETA (NTK * 9 + 262144)
#define SCRATCH_FLOATS (OFF_BETA + 16384)
__device__ float g_scratch[SCRATCH_FLOATS];

// fp16 scratch (halfs)
#define HO_W3   ((size_t)0)
#define HO_WO   ((size_t)12582912)
#define HO_WFB  ((size_t)16777216)
#define HO_X    ((size_t)17301504)
#define HO_FG   ((size_t)19398656)
#define HO_OG   ((size_t)19660800)
#define HBUF_HALFS ((size_t)21757952)
__device__ __half g_hbuf[HBUF_HALFS];

// ---------------------------------------------------------------------------
// helpers
// ---------------------------------------------------------------------------
__device__ __forceinline__ uint32_t smem_u32(const void* p) {
    uint32_t a;
    asm("{ .reg .u64 t; cvta.to.shared.u64 t, %1; cvt.u32.u64 %0, t; }"
        : "=r"(a) : "l"(p));
    return a;
}
__device__ __forceinline__ void cp16(uint32_t dst, const void* src) {
    asm volatile("cp.async.cg.shared.global [%0], [%1], 16;"
                 :: "r"(dst), "l"(src) : "memory");
}
__device__ __forceinline__ void cp4(uint32_t dst, const void* src) {
    asm volatile("cp.async.ca.shared.global [%0], [%1], 4;"
                 :: "r"(dst), "l"(src) : "memory");
}
#define CP_COMMIT() asm volatile("cp.async.commit_group;" ::: "memory")
#define CP_WAIT(n)  asm volatile("cp.async.wait_group %0;" :: "n"(n) : "memory")
#define NBAR(id)    asm volatile("bar.sync %0, 128;" :: "r"(id) : "memory")

#define LDMX4(r0, r1, r2, r3, addr) \
    asm volatile("ldmatrix.sync.aligned.m8n8.x4.shared.b16 {%0,%1,%2,%3}, [%4];" \
                 : "=r"(r0), "=r"(r1), "=r"(r2), "=r"(r3) : "r"(addr))

// gate transform: exp(-expA * softplus_stable(v + dtb))
__device__ __forceinline__ float gate_xform(float v, float dtb, float expA)
{
    float xr = fminf(fmaxf(v + dtb, -20.f), 20.f);
    float sp = log1pf(expf(xr));
    return expf(-expA * sp);
}

// ---------------------------------------------------------------------------
// fp16 GEMM (persistent CTAs): C[M,N](f32) = A[M,K](h, lda) * Bt[N,K](h)^T
// ---------------------------------------------------------------------------
#define H_RS    40
#define H_STAGE (128 * H_RS)
#define H_SMEM  (3 * 2 * H_STAGE * 2)  // 61440 bytes

template <int GPREP>
__global__ __launch_bounds__(256, 2)
void hgemm_k(const __half* __restrict__ A, int lda,
             const __half* __restrict__ Bt, int ldb,
             float* __restrict__ C, int M, int N, int K,
             const float* __restrict__ dtb, const float* __restrict__ alog)
{
    extern __shared__ __half hsm[];

    const int tid  = threadIdx.x;
    const int wid  = tid >> 5;
    const int lane = tid & 31;
    const int wm   = wid >> 1;
    const int wn   = wid & 1;
    const int NT   = K >> 5;
    const int nTileN = N >> 7;
    const int nTiles = (M >> 7) * nTileN;

    for (int tile = blockIdx.x; tile < nTiles; tile += gridDim.x) {
        const int m0 = (tile / nTileN) * 128;
        const int n0 = (tile % nTileN) * 128;

        float acc[2][8][4];
#pragma unroll
        for (int a = 0; a < 2; a++)
#pragma unroll
            for (int b = 0; b < 8; b++)
#pragma unroll
                for (int c = 0; c < 4; c++) acc[a][b][c] = 0.f;

        auto load_stage = [&](int s, int i) {
            const __half* gA = A  + (size_t)m0 * lda + i * 32;
            const __half* gB = Bt + (size_t)n0 * ldb + i * 32;
            __half* dA = hsm + s * 2 * H_STAGE;
            __half* dB = dA + H_STAGE;
#pragma unroll
            for (int t = 0; t < 2; t++) {
                int idx = tid + t * 256;
                int row = idx >> 2;
                int seg = (idx & 3) * 8;
                cp16(smem_u32(dA + row * H_RS + seg),
                     gA + (size_t)row * lda + seg);
                cp16(smem_u32(dB + row * H_RS + seg),
                     gB + (size_t)row * ldb + seg);
            }
            CP_COMMIT();
        };

        load_stage(0, 0);
        load_stage(1, 1);

        for (int i = 0; i < NT; i++) {
            const int s = i % 3;
            if (i + 1 < NT) { CP_WAIT(1); } else { CP_WAIT(0); }
            __syncthreads();

            const uint32_t uA = smem_u32(hsm + s * 2 * H_STAGE);
            const uint32_t uB = uA + H_STAGE * 2;

#pragma unroll
            for (int kk = 0; kk < 32; kk += 16) {
                uint32_t af[2][4];
#pragma unroll
                for (int mt = 0; mt < 2; mt++) {
                    int row = wm * 32 + mt * 16 + (lane & 15);
                    int kof = kk + ((lane >> 4) << 3);
                    LDMX4(af[mt][0], af[mt][1], af[mt][2], af[mt][3],
                          uA + (row * H_RS + kof) * 2);
                }
                uint32_t bf[4][4];
#pragma unroll
                for (int g = 0; g < 4; g++) {
                    int nrow = wn * 64 + g * 16 + ((lane >> 4) << 3) + (lane & 7);
                    int kof = kk + (((lane >> 3) & 1) << 3);
                    LDMX4(bf[g][0], bf[g][1], bf[g][2], bf[g][3],
                          uB + (nrow * H_RS + kof) * 2);
                }
#pragma unroll
                for (int mt = 0; mt < 2; mt++)
#pragma unroll
                    for (int nt = 0; nt < 8; nt++) {
                        int g = nt >> 1, sub = nt & 1;
                        asm volatile(
                            "mma.sync.aligned.m16n8k16.row.col.f32.f16.f16.f32 "
                            "{%0,%1,%2,%3}, {%4,%5,%6,%7}, {%8,%9}, {%0,%1,%2,%3};"
                            : "+f"(acc[mt][nt][0]), "+f"(acc[mt][nt][1]),
                              "+f"(acc[mt][nt][2]), "+f"(acc[mt][nt][3])
                            : "r"(af[mt][0]), "r"(af[mt][1]),
                              "r"(af[mt][2]), "r"(af[mt][3]),
                              "r"(bf[g][sub * 2]), "r"(bf[g][sub * 2 + 1]));
                    }
            }
            if (i + 2 < NT) load_stage((i + 2) % 3, i + 2);
        }

#pragma unroll
        for (int mt = 0; mt < 2; mt++) {
            int r = m0 + wm * 32 + mt * 16 + (lane >> 2);
#pragma unroll
            for (int nt = 0; nt < 8; nt++) {
                int cn = n0 + wn * 64 + nt * 8 + (lane & 3) * 2;
                float v0a = acc[mt][nt][0], v1a = acc[mt][nt][1];
                float v0b = acc[mt][nt][2], v1b = acc[mt][nt][3];
                if (GPREP) {
                    float ea0 = expf(alog[cn >> 7]);
                    float ea1 = expf(alog[(cn + 1) >> 7]);
                    float d0 = dtb[cn], d1 = dtb[cn + 1];
                    v0a = gate_xform(v0a, d0, ea0); v1a = gate_xform(v1a, d1, ea1);
                    v0b = gate_xform(v0b, d0, ea0); v1b = gate_xform(v1b, d1, ea1);
                }
                *(float2*)(C + (size_t)r * N + cn) = make_float2(v0a, v1a);
                *(float2*)(C + (size_t)(r + 8) * N + cn) = make_float2(v0b, v1b);
            }
        }
        __syncthreads();
    }
}

// ---------------------------------------------------------------------------
// transpose to half, 3-way
// ---------------------------------------------------------------------------
__global__ __launch_bounds__(256)
void transpose3_h_k(const float* __restrict__ i0, const float* __restrict__ i1,
                    const float* __restrict__ i2, __half* __restrict__ out,
                    int R, int C)
{
    __shared__ float t[32][33];
    const float* in = (blockIdx.z == 0) ? i0 : (blockIdx.z == 1) ? i1 : i2;
    __half* o = out + (size_t)blockIdx.z * R * C;
    int cb = blockIdx.x * 32, rb = blockIdx.y * 32;
    int x = threadIdx.x & 31, y = threadIdx.x >> 5;
#pragma unroll
    for (int j = 0; j < 32; j += 8)
        t[y + j][x] = in[(size_t)(rb + y + j) * C + cb + x];
    __syncthreads();
#pragma unroll
    for (int j = 0; j < 32; j += 8)
        o[(size_t)(cb + y + j) * R + rb + x] = __float2half_rn(t[x][y + j]);
}

__global__ __launch_bounds__(256)
void transpose_h_k(const float* __restrict__ in, __half* __restrict__ out,
                   int R, int C)
{
    __shared__ float t[32][33];
    int cb = blockIdx.x * 32, rb = blockIdx.y * 32;
    int x = threadIdx.x & 31, y = threadIdx.x >> 5;
#pragma unroll
    for (int j = 0; j < 32; j += 8)
        t[y + j][x] = in[(size_t)(rb + y + j) * C + cb + x];
    __syncthreads();
#pragma unroll
    for (int j = 0; j < 32; j += 8)
        out[(size_t)(cb + y + j) * R + rb + x] = __float2half_rn(t[x][y + j]);
}

__global__ void f2h_k(const float* __restrict__ in, __half* __restrict__ out,
                      int n)
{
    int i = blockIdx.x * 256 + threadIdx.x;
    if (i < n) out[i] = __float2half_rn(in[i]);
}

// ---------------------------------------------------------------------------
// SIMT split-K SGEMM (tall-skinny rank-128 projections), fp32
// ---------------------------------------------------------------------------
template <int ATOMIC>
__global__ __launch_bounds__(256)
void sgemm_k(const float* __restrict__ A, const float* __restrict__ B,
             float* __restrict__ C, int M, int N, int K, int kSplit)
{
    __shared__ __align__(16) float As[8][128];
    __shared__ __align__(16) float Bs[8][128];

    const int tid  = threadIdx.x;
    const int bm   = blockIdx.y;
    const int bn   = blockIdx.x;
    const int k0   = blockIdx.z * kSplit;

    const int arow = tid >> 1;
    const int acol = (tid & 1) << 2;
    const int brow = tid >> 5;
    const int bcol = (tid & 31) << 2;
    const int ty   = tid >> 4;
    const int tx   = tid & 15;

    float acc[8][8];
#pragma unroll
    for (int i = 0; i < 8; i++)
#pragma unroll
        for (int j = 0; j < 8; j++) acc[i][j] = 0.f;

    const float* Ag = A + (size_t)(bm * 128 + arow) * K;
    const float* Bg = B + (size_t)(bn * 128) + bcol;

    for (int kt = 0; kt < kSplit; kt += 8) {
        float4 av = *(const float4*)(Ag + (k0 + kt + acol));
        As[acol + 0][arow] = av.x;
        As[acol + 1][arow] = av.y;
        As[acol + 2][arow] = av.z;
        As[acol + 3][arow] = av.w;
        *(float4*)&Bs[brow][bcol] =
            *(const float4*)(Bg + (size_t)(k0 + kt + brow) * N);
        __syncthreads();

#pragma unroll
        for (int kk = 0; kk < 8; kk++) {
            float4 a0 = *(const float4*)&As[kk][ty * 8];
            float4 a1 = *(const float4*)&As[kk][ty * 8 + 4];
            float4 b0 = *(const float4*)&Bs[kk][tx * 8];
            float4 b1 = *(const float4*)&Bs[kk][tx * 8 + 4];
            float a[8] = {a0.x, a0.y, a0.z, a0.w, a1.x, a1.y, a1.z, a1.w};
            float b[8] = {b0.x, b0.y, b0.z, b0.w, b1.x, b1.y, b1.z, b1.w};
#pragma unroll
            for (int i = 0; i < 8; i++)
#pragma unroll
                for (int j = 0; j < 8; j++)
                    acc[i][j] = fmaf(a[i], b[j], acc[i][j]);
        }
        __syncthreads();
    }

#pragma unroll
    for (int i = 0; i < 8; i++) {
        float* Cp = C + (size_t)(bm * 128 + ty * 8 + i) * N + bn * 128 + tx * 8;
        if (ATOMIC) {
#pragma unroll
            for (int j = 0; j < 8; j++) atomicAdd(Cp + j, acc[i][j]);
        } else {
            *(float4*)(Cp + 0) = make_float4(acc[i][0], acc[i][1], acc[i][2], acc[i][3]);
            *(float4*)(Cp + 4) = make_float4(acc[i][4], acc[i][5], acc[i][6], acc[i][7]);
        }
    }
}

__global__ void zero_k(float* __restrict__ p, int n)
{
    int i = blockIdx.x * 256 + threadIdx.x;
    if (i < n) p[i] = 0.f;
}

__device__ __forceinline__ float block128_sum(float v, float* shm)
{
#pragma unroll
    for (int m = 16; m > 0; m >>= 1) v += __shfl_xor_sync(0xffffffffu, v, m);
    int w = threadIdx.x >> 5;
    if ((threadIdx.x & 31) == 0) shm[w] = v;
    __syncthreads();
    return shm[0] + shm[1] + shm[2] + shm[3];
}

// ---------------------------------------------------------------------------
// fused: depthwise causal conv (K=4) + SiLU + l2norm(q,k).  grid (T, NH).
// ---------------------------------------------------------------------------
__global__ __launch_bounds__(128)
void conv_l2_k(const float* __restrict__ qkv,
               const float* __restrict__ wq, const float* __restrict__ wk,
               const float* __restrict__ wv,
               float* __restrict__ qc, float* __restrict__ kc,
               float* __restrict__ vc)
{
    __shared__ float shm[4];
    int t = blockIdx.x, h = blockIdx.y, d = threadIdx.x;
    int c = h * DH + d;
    float aq = 0.f, ak = 0.f, av = 0.f;
#pragma unroll
    for (int j = 0; j < 4; j++) {
        int tt = t + j - 3;
        if (tt >= 0) {
            size_t base = (size_t)tt * 6144;
            aq = fmaf(wq[j * KD + c], qkv[base + c], aq);
            ak = fmaf(wk[j * KD + c], qkv[base + 2048 + c], ak);
            av = fmaf(wv[j * KD + c], qkv[base + 4096 + c], av);
        }
    }
    aq = aq / (1.f + expf(-aq));
    ak = ak / (1.f + expf(-ak));
    av = av / (1.f + expf(-av));

    size_t idx = (size_t)t * KD + c;
    vc[idx] = av;

    float ssq = block128_sum(aq * aq, shm);
    __syncthreads();
    float ssk = block128_sum(ak * ak, shm);
    qc[idx] = aq * rsqrtf(ssq + 1e-6f) * 0.08838834764831845f;
    kc[idx] = ak * rsqrtf(ssk + 1e-6f);
}

// ---------------------------------------------------------------------------
// beta = sigmoid(x @ Wb)
// ---------------------------------------------------------------------------
__global__ __launch_bounds__(512)
void beta_k(const float* __restrict__ x, const float* __restrict__ Wb,
            float* __restrict__ beta)
{
    __shared__ float sx[DM];
    int t = blockIdx.x;
    for (int i = threadIdx.x; i < DM; i += 512) sx[i] = x[(size_t)t * DM + i];
    __syncthreads();
    int h = threadIdx.x >> 5, lane = threadIdx.x & 31;
    float acc = 0.f;
    for (int k = lane; k < DM; k += 32) acc = fmaf(sx[k], Wb[k * NH + h], acc);
#pragma unroll
    for (int m = 16; m > 0; m >>= 1) acc += __shfl_xor_sync(0xffffffffu, acc, m);
    if (lane == 0) beta[t * NH + h] = 1.f / (1.f + expf(-acc));
}

// ---------------------------------------------------------------------------
// gated delta recurrence v7: split-CTA. Two independent 128-thread pipelines
// per CTA (named barriers 1 and 2), each owning 8 columns + its own 8-stage
// ring (distance 6). Math identical to v6 (2-step lookahead linearization).
// grid 128 x 256.
// ---------------------------------------------------------------------------
__global__ __launch_bounds__(256)
void recur7_k(const float* __restrict__ qf, const float* __restrict__ kf,
              const float* __restrict__ vv, const float* __restrict__ eg,
              const float* __restrict__ beta, float* __restrict__ o)
{
    __shared__ __align__(16) float sq[2][8][128];
    __shared__ __align__(16) float sk[2][8][128];
    __shared__ __align__(16) float se[2][8][128];
    __shared__ __align__(16) float sv[2][8][8];
    __shared__ float sb[2][8];

    const int tid  = threadIdx.x;
    const int half = tid >> 7;           // 0 or 1 (warp-aligned)
    const int htid = tid & 127;
    const int hw   = htid >> 5;          // warp within half, 0..3
    const int lane = tid & 31;
    const int sub  = lane >> 4;
    const int l16  = lane & 15;
    const int colbase = blockIdx.x * 16 + half * 8;
    const int head = (blockIdx.x * 16) >> 7;
    const int col  = colbase + hw * 2 + sub;
    const int hoff = head * DH;
    const int bid  = half + 1;           // named barrier id

    // producer (per half): htid 0..31 q, 32..63 k, 64..95 eg (float4 each),
    // 96..97 v (float4 each, 8 cols), 98 beta (scalar).
    auto issue_stage = [&](int t) {
        int st = t & 7;
        if (htid < 96) {
            int arr = htid >> 5;
            int off = (htid & 31) * 4;
            const float* src = (arr == 0 ? qf : (arr == 1 ? kf : eg))
                               + (size_t)t * KD + hoff + off;
            float* dst = (arr == 0 ? sq[half][st]
                         : (arr == 1 ? sk[half][st] : se[half][st])) + off;
            cp16(smem_u32(dst), src);
        } else if (htid < 98) {
            int off = (htid - 96) * 4;
            cp16(smem_u32(sv[half][st] + off),
                 vv + (size_t)t * KD + colbase + off);
        } else if (htid == 98) {
            cp4(smem_u32(&sb[half][st]), beta + t * NH + head);
        }
        CP_COMMIT();
    };

#pragma unroll
    for (int p = 0; p < 6; p++) issue_stage(p);

    float s[8];
#pragma unroll
    for (int i = 0; i < 8; i++) s[i] = 0.f;

    for (int t = 0; t < T_LEN; t += 2) {
        const int st0 = t & 7;
        const int st1 = (t + 1) & 7;
        CP_WAIT(4);
        NBAR(bid);

        // conflict-free float4 loads (indices l16 and l16+16)
        float k0v[8], k1v[8], q0v[8], q1v[8], e0v[8], e1v[8];
        *(float4*)&k0v[0] = ((const float4*)sk[half][st0])[l16];
        *(float4*)&k0v[4] = ((const float4*)sk[half][st0])[l16 + 16];
        *(float4*)&q0v[0] = ((const float4*)sq[half][st0])[l16];
        *(float4*)&q0v[4] = ((const float4*)sq[half][st0])[l16 + 16];
        *(float4*)&e0v[0] = ((const float4*)se[half][st0])[l16];
        *(float4*)&e0v[4] = ((const float4*)se[half][st0])[l16 + 16];
        *(float4*)&k1v[0] = ((const float4*)sk[half][st1])[l16];
        *(float4*)&k1v[4] = ((const float4*)sk[half][st1])[l16 + 16];
        *(float4*)&q1v[0] = ((const float4*)sq[half][st1])[l16];
        *(float4*)&q1v[4] = ((const float4*)sq[half][st1])[l16 + 16];
        *(float4*)&e1v[0] = ((const float4*)se[half][st1])[l16];
        *(float4*)&e1v[4] = ((const float4*)se[half][st1])[l16 + 16];
        float v0 = sv[half][st0][hw * 2 + sub];
        float v1 = sv[half][st1][hw * 2 + sub];
        float b0 = sb[half][st0];
        float b1 = sb[half][st1];

        // prefetch stages t+6, t+7
        if (t + 6 < T_LEN) issue_stage(t + 6); else CP_COMMIT();
        if (t + 7 < T_LEN) issue_stage(t + 7); else CP_COMMIT();

        // elementwise precomputes: d0 = e0*S, d1 = e1*d0, w = e1*k0
        float d0v[8], d1v[8], wv8[8];
#pragma unroll
        for (int i = 0; i < 8; i++) {
            d0v[i] = e0v[i] * s[i];
            d1v[i] = e1v[i] * d0v[i];
            wv8[i] = e1v[i] * k0v[i];
        }

        // eight partial dots
        float P1 = 0.f, P2 = 0.f, P3 = 0.f, P4 = 0.f;
        float P5 = 0.f, P6 = 0.f, P7 = 0.f, P8 = 0.f;
#pragma unroll
        for (int i = 0; i < 8; i++) {
            P1 = fmaf(k0v[i], d0v[i], P1);
            P2 = fmaf(q0v[i], d0v[i], P2);
            P3 = fmaf(q0v[i], k0v[i], P3);
            P4 = fmaf(k1v[i], d1v[i], P4);
            P5 = fmaf(q1v[i], d1v[i], P5);
            P6 = fmaf(k1v[i], wv8[i], P6);
            P7 = fmaf(q1v[i], wv8[i], P7);
            P8 = fmaf(q1v[i], k1v[i], P8);
        }

        // one butterfly phase, 8 concurrent chains (16-lane groups)
#pragma unroll
        for (int m = 8; m > 0; m >>= 1) {
            P1 += __shfl_xor_sync(0xffffffffu, P1, m);
            P2 += __shfl_xor_sync(0xffffffffu, P2, m);
            P3 += __shfl_xor_sync(0xffffffffu, P3, m);
            P4 += __shfl_xor_sync(0xffffffffu, P4, m);
            P5 += __shfl_xor_sync(0xffffffffu, P5, m);
            P6 += __shfl_xor_sync(0xffffffffu, P6, m);
            P7 += __shfl_xor_sync(0xffffffffu, P7, m);
            P8 += __shfl_xor_sync(0xffffffffu, P8, m);
        }

        // scalar serial tail
        float u0 = b0 * (v0 - P1);
        float o0 = fmaf(P3, u0, P2);
        float r  = fmaf(P6, u0, P4);
        float u1 = b1 * (v1 - r);
        float o1 = fmaf(P8, u1, fmaf(P7, u0, P5));

        // state update: S' = d1 + w*u0 + k1*u1
#pragma unroll
        for (int i = 0; i < 8; i++)
            s[i] = fmaf(k1v[i], u1, fmaf(wv8[i], u0, d1v[i]));

        if (l16 == 0) {
            o[(size_t)t * KD + col] = o0;
            o[(size_t)(t + 1) * KD + col] = o1;
        }
    }
}

// ---------------------------------------------------------------------------
// epilogue: og(half) = o * rsqrt(mean(o^2)+eps) * norm_w * sigmoid(gout)
// ---------------------------------------------------------------------------
__global__ __launch_bounds__(128)
void epi_k(const float* __restrict__ o, const float* __restrict__ gout,
           const float* __restrict__ norm_w, __half* __restrict__ og)
{
    __shared__ float shm[4];
    int t = blockIdx.x, h = blockIdx.y, d = threadIdx.x;
    size_t idx = (size_t)t * KD + h * DH + d;
    float ov = o[idx];
    float ss = block128_sum(ov * ov, shm);
    float rstd = rsqrtf(ss * (1.f / 128.f) + 1e-6f);
    float gate = 1.f / (1.f + expf(-gout[idx]));
    og[idx] = __float2half_rn(ov * rstd * norm_w[d] * gate);
}

// ---------------------------------------------------------------------------
// launch: two-stream DAG. Chain B (gates/weights) overlaps chain A (qkv).
// ---------------------------------------------------------------------------
extern "C" void kernel_launch(void* const* d_in, const int* in_sizes, int n_in,
                              void* d_out, int out_size)
{
    (void)in_sizes; (void)n_in; (void)out_size;
    const float* x      = (const float*)d_in[0];
    const float* Wq     = (const float*)d_in[1];
    const float* Wk     = (const float*)d_in[2];
    const float* Wv     = (const float*)d_in[3];
    const float* conv_q = (const float*)d_in[4];
    const float* conv_k = (const float*)d_in[5];
    const float* conv_v = (const float*)d_in[6];
    const float* Wfa    = (const float*)d_in[7];
    const float* Wfb    = (const float*)d_in[8];
    const float* dt_b   = (const float*)d_in[9];
    const float* A_log  = (const float*)d_in[10];
    const float* Wb     = (const float*)d_in[11];
    const float* Wga    = (const float*)d_in[12];
    const float* Wgb    = (const float*)d_in[13];
    const float* norm_w = (const float*)d_in[14];
    const float* Wo     = (const float*)d_in[15];
    float* out = (float*)d_out;

    float* s = nullptr;
    cudaGetSymbolAddress((void**)&s, g_scratch);
    __half* hb = nullptr;
    cudaGetSymbolAddress((void**)&hb, g_hbuf);

    float* qkv  = s + OFF_QKV;
    float* qc   = s + OFF_QC;
    float* kc   = s + OFF_KC;
    float* vc   = s + OFF_VC;
    float* eg   = s + OFF_EG;
    float* gout = s + OFF_GOUT;
    float* o    = s + OFF_O;
    float* fa   = s + OFF_FA;
    float* beta = s + OFF_BETA;

    __half* W3   = hb + HO_W3;
    __half* WOh  = hb + HO_WO;
    __half* WFBh = hb + HO_WFB;
    __half* xh   = hb + HO_X;
    __half* fgh  = hb + HO_FG;
    __half* ogh  = hb + HO_OG;

    static cudaStream_t sB = nullptr;
    static cudaEvent_t eFork = nullptr, eJoin = nullptr;
    if (!sB) {
        cudaStreamCreateWithFlags(&sB, cudaStreamNonBlocking);
        cudaEventCreateWithFlags(&eFork, cudaEventDisableTiming);
        cudaEventCreateWithFlags(&eJoin, cudaEventDisableTiming);
    }

    static bool attr_done = false;
    if (!attr_done) {
        cudaFuncSetAttribute(hgemm_k<0>,
                             cudaFuncAttributeMaxDynamicSharedMemorySize, H_SMEM);
        cudaFuncSetAttribute(hgemm_k<1>,
                             cudaFuncAttributeMaxDynamicSharedMemorySize, H_SMEM);
        attr_done = true;
    }

    // ---- fork chain B off the (captured) default stream ----
    cudaEventRecord(eFork, 0);
    cudaStreamWaitEvent(sB, eFork, 0);

    // ---- chain A (default stream): qkv path ----
    transpose3_h_k<<<dim3(64, 64, 3), 256>>>(Wq, Wk, Wv, W3, DM, KD);
    f2h_k<<<(unsigned)(NTK / 256), 256>>>(x, xh, (int)NTK);
    hgemm_k<0><<<296, 256, H_SMEM>>>(xh, DM, W3, DM, qkv,
                                     T_LEN, 6144, DM, nullptr, nullptr);
    conv_l2_k<<<dim3(T_LEN, NH), 128>>>(qkv, conv_q, conv_k, conv_v,
                                        qc, kc, vc);

    // ---- chain B (stream sB): gates, beta, weight transposes ----
    zero_k<<<1024, 256, 0, sB>>>(fa, 262144);
    sgemm_k<1><<<dim3(1, 8, 16), 256, 0, sB>>>(x, Wfa, fa,
                                               T_LEN, DH, DM, 128);
    sgemm_k<1><<<dim3(1, 8, 16), 256, 0, sB>>>(x, Wga, fa + 131072,
                                               T_LEN, DH, DM, 128);
    f2h_k<<<1024, 256, 0, sB>>>(fa, fgh, 262144);
    transpose3_h_k<<<dim3(64, 4, 2), 256, 0, sB>>>(Wfb, Wgb, Wgb, WFBh, DH, KD);
    transpose_h_k<<<dim3(64, 64), 256, 0, sB>>>(Wo, WOh, KD, DM);
    hgemm_k<1><<<128, 256, H_SMEM, sB>>>(fgh, DH, WFBh, DH, eg,
                                         T_LEN, KD, DH, dt_b, A_log);
    hgemm_k<0><<<128, 256, H_SMEM, sB>>>(fgh + 131072, DH,
                                         WFBh + 262144, DH, gout,
                                         T_LEN, KD, DH, nullptr, nullptr);
    beta_k<<<T_LEN, 512, 0, sB>>>(x, Wb, beta);
    cudaEventRecord(eJoin, sB);

    // ---- join, then recurrence + epilogue (default stream) ----
    cudaStreamWaitEvent(0, eJoin, 0);
    recur7_k<<<128, 256>>>(qc, kc, vc, eg, beta, o);
    epi_k<<<dim3(T_LEN, NH), 128>>>(o, gout, norm_w, ogh);
    hgemm_k<0><<<128, 256, H_SMEM>>>(ogh, KD, WOh, KD, out,
                                     T_LEN, DM, KD, nullptr, nullptr);
}

// round 16
// speedup vs baseline: 1.0304x; 1.0304x over previous
#include <cuda_runtime.h>
#include <cuda_fp16.h>
#include <math.h>
#include <cstdint>

// ---------------------------------------------------------------------------
// KimiDeltaAttention  (B=1, T=1024, DM=2048, H=16, DH=128, KD=2048, KC=4)
// Round 16: revert split-CTA regression; recurrence v8 = v6 math with a
// 16-stage ring and ONE barrier/wait per FOUR timesteps (two lookahead
// pairs per iteration). Everything else identical to the 710us R14 build.
// ---------------------------------------------------------------------------

#define T_LEN 1024
#define DM    2048
#define NH    16
#define DH    128
#define KD    2048

static constexpr size_t NTK = (size_t)T_LEN * KD;   // 2097152

// fp32 scratch
#define OFF_QKV  ((size_t)0)
#define OFF_QC   (NTK * 3)
#define OFF_KC   (NTK * 4)
#define OFF_VC   (NTK * 5)
#define OFF_EG   (NTK * 6)
#define OFF_GOUT (NTK * 7)
#define OFF_O    (NTK * 8)
#define OFF_FA   (NTK * 9)
#define OFF_BETA (NTK * 9 + 262144)
#define SCRATCH_FLOATS (OFF_BETA + 16384)
__device__ float g_scratch[SCRATCH_FLOATS];

// fp16 scratch (halfs)
#define HO_W3   ((size_t)0)
#define HO_WO   ((size_t)12582912)
#define HO_WFB  ((size_t)16777216)
#define HO_X    ((size_t)17301504)
#define HO_FG   ((size_t)19398656)
#define HO_OG   ((size_t)19660800)
#define HBUF_HALFS ((size_t)21757952)
__device__ __half g_hbuf[HBUF_HALFS];

// ---------------------------------------------------------------------------
// helpers
// ---------------------------------------------------------------------------
__device__ __forceinline__ uint32_t smem_u32(const void* p) {
    uint32_t a;
    asm("{ .reg .u64 t; cvta.to.shared.u64 t, %1; cvt.u32.u64 %0, t; }"
        : "=r"(a) : "l"(p));
    return a;
}
__device__ __forceinline__ void cp16(uint32_t dst, const void* src) {
    asm volatile("cp.async.cg.shared.global [%0], [%1], 16;"
                 :: "r"(dst), "l"(src) : "memory");
}
__device__ __forceinline__ void cp4(uint32_t dst, const void* src) {
    asm volatile("cp.async.ca.shared.global [%0], [%1], 4;"
                 :: "r"(dst), "l"(src) : "memory");
}
#define CP_COMMIT() asm volatile("cp.async.commit_group;" ::: "memory")
#define CP_WAIT(n)  asm volatile("cp.async.wait_group %0;" :: "n"(n) : "memory")

#define LDMX4(r0, r1, r2, r3, addr) \
    asm volatile("ldmatrix.sync.aligned.m8n8.x4.shared.b16 {%0,%1,%2,%3}, [%4];" \
                 : "=r"(r0), "=r"(r1), "=r"(r2), "=r"(r3) : "r"(addr))

// gate transform: exp(-expA * softplus_stable(v + dtb))
__device__ __forceinline__ float gate_xform(float v, float dtb, float expA)
{
    float xr = fminf(fmaxf(v + dtb, -20.f), 20.f);
    float sp = log1pf(expf(xr));
    return expf(-expA * sp);
}

// ---------------------------------------------------------------------------
// fp16 GEMM (persistent CTAs): C[M,N](f32) = A[M,K](h, lda) * Bt[N,K](h)^T
// ---------------------------------------------------------------------------
#define H_RS    40
#define H_STAGE (128 * H_RS)
#define H_SMEM  (3 * 2 * H_STAGE * 2)  // 61440 bytes

template <int GPREP>
__global__ __launch_bounds__(256, 2)
void hgemm_k(const __half* __restrict__ A, int lda,
             const __half* __restrict__ Bt, int ldb,
             float* __restrict__ C, int M, int N, int K,
             const float* __restrict__ dtb, const float* __restrict__ alog)
{
    extern __shared__ __half hsm[];

    const int tid  = threadIdx.x;
    const int wid  = tid >> 5;
    const int lane = tid & 31;
    const int wm   = wid >> 1;
    const int wn   = wid & 1;
    const int NT   = K >> 5;
    const int nTileN = N >> 7;
    const int nTiles = (M >> 7) * nTileN;

    for (int tile = blockIdx.x; tile < nTiles; tile += gridDim.x) {
        const int m0 = (tile / nTileN) * 128;
        const int n0 = (tile % nTileN) * 128;

        float acc[2][8][4];
#pragma unroll
        for (int a = 0; a < 2; a++)
#pragma unroll
            for (int b = 0; b < 8; b++)
#pragma unroll
                for (int c = 0; c < 4; c++) acc[a][b][c] = 0.f;

        auto load_stage = [&](int s, int i) {
            const __half* gA = A  + (size_t)m0 * lda + i * 32;
            const __half* gB = Bt + (size_t)n0 * ldb + i * 32;
            __half* dA = hsm + s * 2 * H_STAGE;
            __half* dB = dA + H_STAGE;
#pragma unroll
            for (int t = 0; t < 2; t++) {
                int idx = tid + t * 256;
                int row = idx >> 2;
                int seg = (idx & 3) * 8;
                cp16(smem_u32(dA + row * H_RS + seg),
                     gA + (size_t)row * lda + seg);
                cp16(smem_u32(dB + row * H_RS + seg),
                     gB + (size_t)row * ldb + seg);
            }
            CP_COMMIT();
        };

        load_stage(0, 0);
        load_stage(1, 1);

        for (int i = 0; i < NT; i++) {
            const int s = i % 3;
            if (i + 1 < NT) { CP_WAIT(1); } else { CP_WAIT(0); }
            __syncthreads();

            const uint32_t uA = smem_u32(hsm + s * 2 * H_STAGE);
            const uint32_t uB = uA + H_STAGE * 2;

#pragma unroll
            for (int kk = 0; kk < 32; kk += 16) {
                uint32_t af[2][4];
#pragma unroll
                for (int mt = 0; mt < 2; mt++) {
                    int row = wm * 32 + mt * 16 + (lane & 15);
                    int kof = kk + ((lane >> 4) << 3);
                    LDMX4(af[mt][0], af[mt][1], af[mt][2], af[mt][3],
                          uA + (row * H_RS + kof) * 2);
                }
                uint32_t bf[4][4];
#pragma unroll
                for (int g = 0; g < 4; g++) {
                    int nrow = wn * 64 + g * 16 + ((lane >> 4) << 3) + (lane & 7);
                    int kof = kk + (((lane >> 3) & 1) << 3);
                    LDMX4(bf[g][0], bf[g][1], bf[g][2], bf[g][3],
                          uB + (nrow * H_RS + kof) * 2);
                }
#pragma unroll
                for (int mt = 0; mt < 2; mt++)
#pragma unroll
                    for (int nt = 0; nt < 8; nt++) {
                        int g = nt >> 1, sub = nt & 1;
                        asm volatile(
                            "mma.sync.aligned.m16n8k16.row.col.f32.f16.f16.f32 "
                            "{%0,%1,%2,%3}, {%4,%5,%6,%7}, {%8,%9}, {%0,%1,%2,%3};"
                            : "+f"(acc[mt][nt][0]), "+f"(acc[mt][nt][1]),
                              "+f"(acc[mt][nt][2]), "+f"(acc[mt][nt][3])
                            : "r"(af[mt][0]), "r"(af[mt][1]),
                              "r"(af[mt][2]), "r"(af[mt][3]),
                              "r"(bf[g][sub * 2]), "r"(bf[g][sub * 2 + 1]));
                    }
            }
            if (i + 2 < NT) load_stage((i + 2) % 3, i + 2);
        }

#pragma unroll
        for (int mt = 0; mt < 2; mt++) {
            int r = m0 + wm * 32 + mt * 16 + (lane >> 2);
#pragma unroll
            for (int nt = 0; nt < 8; nt++) {
                int cn = n0 + wn * 64 + nt * 8 + (lane & 3) * 2;
                float v0a = acc[mt][nt][0], v1a = acc[mt][nt][1];
                float v0b = acc[mt][nt][2], v1b = acc[mt][nt][3];
                if (GPREP) {
                    float ea0 = expf(alog[cn >> 7]);
                    float ea1 = expf(alog[(cn + 1) >> 7]);
                    float d0 = dtb[cn], d1 = dtb[cn + 1];
                    v0a = gate_xform(v0a, d0, ea0); v1a = gate_xform(v1a, d1, ea1);
                    v0b = gate_xform(v0b, d0, ea0); v1b = gate_xform(v1b, d1, ea1);
                }
                *(float2*)(C + (size_t)r * N + cn) = make_float2(v0a, v1a);
                *(float2*)(C + (size_t)(r + 8) * N + cn) = make_float2(v0b, v1b);
            }
        }
        __syncthreads();
    }
}

// ---------------------------------------------------------------------------
// transpose to half, 3-way
// ---------------------------------------------------------------------------
__global__ __launch_bounds__(256)
void transpose3_h_k(const float* __restrict__ i0, const float* __restrict__ i1,
                    const float* __restrict__ i2, __half* __restrict__ out,
                    int R, int C)
{
    __shared__ float t[32][33];
    const float* in = (blockIdx.z == 0) ? i0 : (blockIdx.z == 1) ? i1 : i2;
    __half* o = out + (size_t)blockIdx.z * R * C;
    int cb = blockIdx.x * 32, rb = blockIdx.y * 32;
    int x = threadIdx.x & 31, y = threadIdx.x >> 5;
#pragma unroll
    for (int j = 0; j < 32; j += 8)
        t[y + j][x] = in[(size_t)(rb + y + j) * C + cb + x];
    __syncthreads();
#pragma unroll
    for (int j = 0; j < 32; j += 8)
        o[(size_t)(cb + y + j) * R + rb + x] = __float2half_rn(t[x][y + j]);
}

__global__ __launch_bounds__(256)
void transpose_h_k(const float* __restrict__ in, __half* __restrict__ out,
                   int R, int C)
{
    __shared__ float t[32][33];
    int cb = blockIdx.x * 32, rb = blockIdx.y * 32;
    int x = threadIdx.x & 31, y = threadIdx.x >> 5;
#pragma unroll
    for (int j = 0; j < 32; j += 8)
        t[y + j][x] = in[(size_t)(rb + y + j) * C + cb + x];
    __syncthreads();
#pragma unroll
    for (int j = 0; j < 32; j += 8)
        out[(size_t)(cb + y + j) * R + rb + x] = __float2half_rn(t[x][y + j]);
}

__global__ void f2h_k(const float* __restrict__ in, __half* __restrict__ out,
                      int n)
{
    int i = blockIdx.x * 256 + threadIdx.x;
    if (i < n) out[i] = __float2half_rn(in[i]);
}

// ---------------------------------------------------------------------------
// SIMT split-K SGEMM (tall-skinny rank-128 projections), fp32
// ---------------------------------------------------------------------------
template <int ATOMIC>
__global__ __launch_bounds__(256)
void sgemm_k(const float* __restrict__ A, const float* __restrict__ B,
             float* __restrict__ C, int M, int N, int K, int kSplit)
{
    __shared__ __align__(16) float As[8][128];
    __shared__ __align__(16) float Bs[8][128];

    const int tid  = threadIdx.x;
    const int bm   = blockIdx.y;
    const int bn   = blockIdx.x;
    const int k0   = blockIdx.z * kSplit;

    const int arow = tid >> 1;
    const int acol = (tid & 1) << 2;
    const int brow = tid >> 5;
    const int bcol = (tid & 31) << 2;
    const int ty   = tid >> 4;
    const int tx   = tid & 15;

    float acc[8][8];
#pragma unroll
    for (int i = 0; i < 8; i++)
#pragma unroll
        for (int j = 0; j < 8; j++) acc[i][j] = 0.f;

    const float* Ag = A + (size_t)(bm * 128 + arow) * K;
    const float* Bg = B + (size_t)(bn * 128) + bcol;

    for (int kt = 0; kt < kSplit; kt += 8) {
        float4 av = *(const float4*)(Ag + (k0 + kt + acol));
        As[acol + 0][arow] = av.x;
        As[acol + 1][arow] = av.y;
        As[acol + 2][arow] = av.z;
        As[acol + 3][arow] = av.w;
        *(float4*)&Bs[brow][bcol] =
            *(const float4*)(Bg + (size_t)(k0 + kt + brow) * N);
        __syncthreads();

#pragma unroll
        for (int kk = 0; kk < 8; kk++) {
            float4 a0 = *(const float4*)&As[kk][ty * 8];
            float4 a1 = *(const float4*)&As[kk][ty * 8 + 4];
            float4 b0 = *(const float4*)&Bs[kk][tx * 8];
            float4 b1 = *(const float4*)&Bs[kk][tx * 8 + 4];
            float a[8] = {a0.x, a0.y, a0.z, a0.w, a1.x, a1.y, a1.z, a1.w};
            float b[8] = {b0.x, b0.y, b0.z, b0.w, b1.x, b1.y, b1.z, b1.w};
#pragma unroll
            for (int i = 0; i < 8; i++)
#pragma unroll
                for (int j = 0; j < 8; j++)
                    acc[i][j] = fmaf(a[i], b[j], acc[i][j]);
        }
        __syncthreads();
    }

#pragma unroll
    for (int i = 0; i < 8; i++) {
        float* Cp = C + (size_t)(bm * 128 + ty * 8 + i) * N + bn * 128 + tx * 8;
        if (ATOMIC) {
#pragma unroll
            for (int j = 0; j < 8; j++) atomicAdd(Cp + j, acc[i][j]);
        } else {
            *(float4*)(Cp + 0) = make_float4(acc[i][0], acc[i][1], acc[i][2], acc[i][3]);
            *(float4*)(Cp + 4) = make_float4(acc[i][4], acc[i][5], acc[i][6], acc[i][7]);
        }
    }
}

__global__ void zero_k(float* __restrict__ p, int n)
{
    int i = blockIdx.x * 256 + threadIdx.x;
    if (i < n) p[i] = 0.f;
}

__device__ __forceinline__ float block128_sum(float v, float* shm)
{
#pragma unroll
    for (int m = 16; m > 0; m >>= 1) v += __shfl_xor_sync(0xffffffffu, v, m);
    int w = threadIdx.x >> 5;
    if ((threadIdx.x & 31) == 0) shm[w] = v;
    __syncthreads();
    return shm[0] + shm[1] + shm[2] + shm[3];
}

// ---------------------------------------------------------------------------
// fused: depthwise causal conv (K=4) + SiLU + l2norm(q,k).  grid (T, NH).
// ---------------------------------------------------------------------------
__global__ __launch_bounds__(128)
void conv_l2_k(const float* __restrict__ qkv,
               const float* __restrict__ wq, const float* __restrict__ wk,
               const float* __restrict__ wv,
               float* __restrict__ qc, float* __restrict__ kc,
               float* __restrict__ vc)
{
    __shared__ float shm[4];
    int t = blockIdx.x, h = blockIdx.y, d = threadIdx.x;
    int c = h * DH + d;
    float aq = 0.f, ak = 0.f, av = 0.f;
#pragma unroll
    for (int j = 0; j < 4; j++) {
        int tt = t + j - 3;
        if (tt >= 0) {
            size_t base = (size_t)tt * 6144;
            aq = fmaf(wq[j * KD + c], qkv[base + c], aq);
            ak = fmaf(wk[j * KD + c], qkv[base + 2048 + c], ak);
            av = fmaf(wv[j * KD + c], qkv[base + 4096 + c], av);
        }
    }
    aq = aq / (1.f + expf(-aq));
    ak = ak / (1.f + expf(-ak));
    av = av / (1.f + expf(-av));

    size_t idx = (size_t)t * KD + c;
    vc[idx] = av;

    float ssq = block128_sum(aq * aq, shm);
    __syncthreads();
    float ssk = block128_sum(ak * ak, shm);
    qc[idx] = aq * rsqrtf(ssq + 1e-6f) * 0.08838834764831845f;
    kc[idx] = ak * rsqrtf(ssk + 1e-6f);
}

// ---------------------------------------------------------------------------
// beta = sigmoid(x @ Wb)
// ---------------------------------------------------------------------------
__global__ __launch_bounds__(512)
void beta_k(const float* __restrict__ x, const float* __restrict__ Wb,
            float* __restrict__ beta)
{
    __shared__ float sx[DM];
    int t = blockIdx.x;
    for (int i = threadIdx.x; i < DM; i += 512) sx[i] = x[(size_t)t * DM + i];
    __syncthreads();
    int h = threadIdx.x >> 5, lane = threadIdx.x & 31;
    float acc = 0.f;
    for (int k = lane; k < DM; k += 32) acc = fmaf(sx[k], Wb[k * NH + h], acc);
#pragma unroll
    for (int m = 16; m > 0; m >>= 1) acc += __shfl_xor_sync(0xffffffffu, acc, m);
    if (lane == 0) beta[t * NH + h] = 1.f / (1.f + expf(-acc));
}

// ---------------------------------------------------------------------------
// gated delta recurrence v8: v6 math (2-step lookahead), 16-stage ring,
// ONE CP_WAIT+__syncthreads per FOUR timesteps (two pairs / iteration).
// Conflict-free lane permutation (float4 idx l16, l16+16). grid 128 x 256.
// ---------------------------------------------------------------------------
__device__ __forceinline__ void look2_step(
    const float* k0v, const float* k1v, const float* q0v, const float* q1v,
    const float* e0v, const float* e1v, float v0, float v1, float b0, float b1,
    float* s, float* o0p, float* o1p)
{
    float d0v[8], d1v[8], wv8[8];
#pragma unroll
    for (int i = 0; i < 8; i++) {
        d0v[i] = e0v[i] * s[i];
        d1v[i] = e1v[i] * d0v[i];
        wv8[i] = e1v[i] * k0v[i];
    }

    float P1 = 0.f, P2 = 0.f, P3 = 0.f, P4 = 0.f;
    float P5 = 0.f, P6 = 0.f, P7 = 0.f, P8 = 0.f;
#pragma unroll
    for (int i = 0; i < 8; i++) {
        P1 = fmaf(k0v[i], d0v[i], P1);
        P2 = fmaf(q0v[i], d0v[i], P2);
        P3 = fmaf(q0v[i], k0v[i], P3);
        P4 = fmaf(k1v[i], d1v[i], P4);
        P5 = fmaf(q1v[i], d1v[i], P5);
        P6 = fmaf(k1v[i], wv8[i], P6);
        P7 = fmaf(q1v[i], wv8[i], P7);
        P8 = fmaf(q1v[i], k1v[i], P8);
    }

#pragma unroll
    for (int m = 8; m > 0; m >>= 1) {
        P1 += __shfl_xor_sync(0xffffffffu, P1, m);
        P2 += __shfl_xor_sync(0xffffffffu, P2, m);
        P3 += __shfl_xor_sync(0xffffffffu, P3, m);
        P4 += __shfl_xor_sync(0xffffffffu, P4, m);
        P5 += __shfl_xor_sync(0xffffffffu, P5, m);
        P6 += __shfl_xor_sync(0xffffffffu, P6, m);
        P7 += __shfl_xor_sync(0xffffffffu, P7, m);
        P8 += __shfl_xor_sync(0xffffffffu, P8, m);
    }

    float u0 = b0 * (v0 - P1);
    float o0 = fmaf(P3, u0, P2);
    float r  = fmaf(P6, u0, P4);
    float u1 = b1 * (v1 - r);
    float o1 = fmaf(P8, u1, fmaf(P7, u0, P5));

#pragma unroll
    for (int i = 0; i < 8; i++)
        s[i] = fmaf(k1v[i], u1, fmaf(wv8[i], u0, d1v[i]));

    *o0p = o0; *o1p = o1;
}

__global__ __launch_bounds__(256)
void recur8_k(const float* __restrict__ qf, const float* __restrict__ kf,
              const float* __restrict__ vv, const float* __restrict__ eg,
              const float* __restrict__ beta, float* __restrict__ o)
{
    __shared__ __align__(16) float sq[16][128];
    __shared__ __align__(16) float sk[16][128];
    __shared__ __align__(16) float se[16][128];
    __shared__ __align__(16) float sv[16][16];
    __shared__ float sb[16];

    const int tid  = threadIdx.x;
    const int wid  = tid >> 5;
    const int lane = tid & 31;
    const int sub  = lane >> 4;
    const int l16  = lane & 15;
    const int colbase = blockIdx.x * 16;
    const int head = colbase >> 7;
    const int col  = colbase + wid * 2 + sub;
    const int hoff = head * DH;

    auto issue_stage = [&](int t) {
        int st = t & 15;
        if (tid < 96) {
            int arr = tid >> 5;
            int off = (tid & 31) * 4;
            const float* src = (arr == 0 ? qf : (arr == 1 ? kf : eg))
                               + (size_t)t * KD + hoff + off;
            float* dst = (arr == 0 ? sq[st] : (arr == 1 ? sk[st] : se[st])) + off;
            cp16(smem_u32(dst), src);
        } else if (tid < 100) {
            int off = (tid - 96) * 4;
            cp16(smem_u32(sv[st] + off),
                 vv + (size_t)t * KD + colbase + off);
        } else if (tid == 100) {
            cp4(smem_u32(&sb[st]), beta + t * NH + head);
        }
        CP_COMMIT();
    };

    // prologue: stages 0..7 in flight
#pragma unroll
    for (int p = 0; p < 8; p++) issue_stage(p);

    float s[8];
#pragma unroll
    for (int i = 0; i < 8; i++) s[i] = 0.f;

    for (int t = 0; t < T_LEN; t += 4) {
        CP_WAIT(4);                 // stages t..t+3 landed (4 younger pending)
        __syncthreads();

        const int st0 = t & 15, st1 = (t + 1) & 15;
        const int st2 = (t + 2) & 15, st3 = (t + 3) & 15;

        // pair A operands (conflict-free: float4 idx l16 and l16+16)
        float k0v[8], k1v[8], q0v[8], q1v[8], e0v[8], e1v[8];
        *(float4*)&k0v[0] = ((const float4*)sk[st0])[l16];
        *(float4*)&k0v[4] = ((const float4*)sk[st0])[l16 + 16];
        *(float4*)&q0v[0] = ((const float4*)sq[st0])[l16];
        *(float4*)&q0v[4] = ((const float4*)sq[st0])[l16 + 16];
        *(float4*)&e0v[0] = ((const float4*)se[st0])[l16];
        *(float4*)&e0v[4] = ((const float4*)se[st0])[l16 + 16];
        *(float4*)&k1v[0] = ((const float4*)sk[st1])[l16];
        *(float4*)&k1v[4] = ((const float4*)sk[st1])[l16 + 16];
        *(float4*)&q1v[0] = ((const float4*)sq[st1])[l16];
        *(float4*)&q1v[4] = ((const float4*)sq[st1])[l16 + 16];
        *(float4*)&e1v[0] = ((const float4*)se[st1])[l16];
        *(float4*)&e1v[4] = ((const float4*)se[st1])[l16 + 16];
        float v0 = sv[st0][wid * 2 + sub];
        float v1 = sv[st1][wid * 2 + sub];
        float b0 = sb[st0];
        float b1 = sb[st1];

        // prefetch stages t+8..t+11 (slots consumed two barriers ago)
        if (t + 8  < T_LEN) issue_stage(t + 8);  else CP_COMMIT();
        if (t + 9  < T_LEN) issue_stage(t + 9);  else CP_COMMIT();
        if (t + 10 < T_LEN) issue_stage(t + 10); else CP_COMMIT();
        if (t + 11 < T_LEN) issue_stage(t + 11); else CP_COMMIT();

        float o0, o1;
        look2_step(k0v, k1v, q0v, q1v, e0v, e1v, v0, v1, b0, b1, s, &o0, &o1);

        // pair B operands
        float k2v[8], k3v[8], q2v[8], q3v[8], e2v[8], e3v[8];
        *(float4*)&k2v[0] = ((const float4*)sk[st2])[l16];
        *(float4*)&k2v[4] = ((const float4*)sk[st2])[l16 + 16];
        *(float4*)&q2v[0] = ((const float4*)sq[st2])[l16];
        *(float4*)&q2v[4] = ((const float4*)sq[st2])[l16 + 16];
        *(float4*)&e2v[0] = ((const float4*)se[st2])[l16];
        *(float4*)&e2v[4] = ((const float4*)se[st2])[l16 + 16];
        *(float4*)&k3v[0] = ((const float4*)sk[st3])[l16];
        *(float4*)&k3v[4] = ((const float4*)sk[st3])[l16 + 16];
        *(float4*)&q3v[0] = ((const float4*)sq[st3])[l16];
        *(float4*)&q3v[4] = ((const float4*)sq[st3])[l16 + 16];
        *(float4*)&e3v[0] = ((const float4*)se[st3])[l16];
        *(float4*)&e3v[4] = ((const float4*)se[st3])[l16 + 16];
        float v2 = sv[st2][wid * 2 + sub];
        float v3 = sv[st3][wid * 2 + sub];
        float b2 = sb[st2];
        float b3 = sb[st3];

        float o2, o3;
        look2_step(k2v, k3v, q2v, q3v, e2v, e3v, v2, v3, b2, b3, s, &o2, &o3);

        if (l16 == 0) {
            o[(size_t)t * KD + col] = o0;
            o[(size_t)(t + 1) * KD + col] = o1;
            o[(size_t)(t + 2) * KD + col] = o2;
            o[(size_t)(t + 3) * KD + col] = o3;
        }
    }
}

// ---------------------------------------------------------------------------
// epilogue: og(half) = o * rsqrt(mean(o^2)+eps) * norm_w * sigmoid(gout)
// ---------------------------------------------------------------------------
__global__ __launch_bounds__(128)
void epi_k(const float* __restrict__ o, const float* __restrict__ gout,
           const float* __restrict__ norm_w, __half* __restrict__ og)
{
    __shared__ float shm[4];
    int t = blockIdx.x, h = blockIdx.y, d = threadIdx.x;
    size_t idx = (size_t)t * KD + h * DH + d;
    float ov = o[idx];
    float ss = block128_sum(ov * ov, shm);
    float rstd = rsqrtf(ss * (1.f / 128.f) + 1e-6f);
    float gate = 1.f / (1.f + expf(-gout[idx]));
    og[idx] = __float2half_rn(ov * rstd * norm_w[d] * gate);
}

// ---------------------------------------------------------------------------
// launch: two-stream DAG. Chain B (gates/weights) overlaps chain A (qkv).
// ---------------------------------------------------------------------------
extern "C" void kernel_launch(void* const* d_in, const int* in_sizes, int n_in,
                              void* d_out, int out_size)
{
    (void)in_sizes; (void)n_in; (void)out_size;
    const float* x      = (const float*)d_in[0];
    const float* Wq     = (const float*)d_in[1];
    const float* Wk     = (const float*)d_in[2];
    const float* Wv     = (const float*)d_in[3];
    const float* conv_q = (const float*)d_in[4];
    const float* conv_k = (const float*)d_in[5];
    const float* conv_v = (const float*)d_in[6];
    const float* Wfa    = (const float*)d_in[7];
    const float* Wfb    = (const float*)d_in[8];
    const float* dt_b   = (const float*)d_in[9];
    const float* A_log  = (const float*)d_in[10];
    const float* Wb     = (const float*)d_in[11];
    const float* Wga    = (const float*)d_in[12];
    const float* Wgb    = (const float*)d_in[13];
    const float* norm_w = (const float*)d_in[14];
    const float* Wo     = (const float*)d_in[15];
    float* out = (float*)d_out;

    float* s = nullptr;
    cudaGetSymbolAddress((void**)&s, g_scratch);
    __half* hb = nullptr;
    cudaGetSymbolAddress((void**)&hb, g_hbuf);

    float* qkv  = s + OFF_QKV;
    float* qc   = s + OFF_QC;
    float* kc   = s + OFF_KC;
    float* vc   = s + OFF_VC;
    float* eg   = s + OFF_EG;
    float* gout = s + OFF_GOUT;
    float* o    = s + OFF_O;
    float* fa   = s + OFF_FA;
    float* beta = s + OFF_BETA;

    __half* W3   = hb + HO_W3;
    __half* WOh  = hb + HO_WO;
    __half* WFBh = hb + HO_WFB;
    __half* xh   = hb + HO_X;
    __half* fgh  = hb + HO_FG;
    __half* ogh  = hb + HO_OG;

    static cudaStream_t sB = nullptr;
    static cudaEvent_t eFork = nullptr, eJoin = nullptr;
    if (!sB) {
        cudaStreamCreateWithFlags(&sB, cudaStreamNonBlocking);
        cudaEventCreateWithFlags(&eFork, cudaEventDisableTiming);
        cudaEventCreateWithFlags(&eJoin, cudaEventDisableTiming);
    }

    static bool attr_done = false;
    if (!attr_done) {
        cudaFuncSetAttribute(hgemm_k<0>,
                             cudaFuncAttributeMaxDynamicSharedMemorySize, H_SMEM);
        cudaFuncSetAttribute(hgemm_k<1>,
                             cudaFuncAttributeMaxDynamicSharedMemorySize, H_SMEM);
        attr_done = true;
    }

    // ---- fork chain B off the (captured) default stream ----
    cudaEventRecord(eFork, 0);
    cudaStreamWaitEvent(sB, eFork, 0);

    // ---- chain A (default stream): qkv path ----
    transpose3_h_k<<<dim3(64, 64, 3), 256>>>(Wq, Wk, Wv, W3, DM, KD);
    f2h_k<<<(unsigned)(NTK / 256), 256>>>(x, xh, (int)NTK);
    hgemm_k<0><<<296, 256, H_SMEM>>>(xh, DM, W3, DM, qkv,
                                     T_LEN, 6144, DM, nullptr, nullptr);
    conv_l2_k<<<dim3(T_LEN, NH), 128>>>(qkv, conv_q, conv_k, conv_v,
                                        qc, kc, vc);

    // ---- chain B (stream sB): gates, beta, weight transposes ----
    zero_k<<<1024, 256, 0, sB>>>(fa, 262144);
    sgemm_k<1><<<dim3(1, 8, 16), 256, 0, sB>>>(x, Wfa, fa,
                                               T_LEN, DH, DM, 128);
    sgemm_k<1><<<dim3(1, 8, 16), 256, 0, sB>>>(x, Wga, fa + 131072,
                                               T_LEN, DH, DM, 128);
    f2h_k<<<1024, 256, 0, sB>>>(fa, fgh, 262144);
    transpose3_h_k<<<dim3(64, 4, 2), 256, 0, sB>>>(Wfb, Wgb, Wgb, WFBh, DH, KD);
    transpose_h_k<<<dim3(64, 64), 256, 0, sB>>>(Wo, WOh, KD, DM);
    hgemm_k<1><<<128, 256, H_SMEM, sB>>>(fgh, DH, WFBh, DH, eg,
                                         T_LEN, KD, DH, dt_b, A_log);
    hgemm_k<0><<<128, 256, H_SMEM, sB>>>(fgh + 131072, DH,
                                         WFBh + 262144, DH, gout,
                                         T_LEN, KD, DH, nullptr, nullptr);
    beta_k<<<T_LEN, 512, 0, sB>>>(x, Wb, beta);
    cudaEventRecord(eJoin, sB);

    // ---- join, then recurrence + epilogue (default stream) ----
    cudaStreamWaitEvent(0, eJoin, 0);
    recur8_k<<<128, 256>>>(qc, kc, vc, eg, beta, o);
    epi_k<<<dim3(T_LEN, NH), 128>>>(o, gout, norm_w, ogh);
    hgemm_k<0><<<128, 256, H_SMEM>>>(ogh, KD, WOh, KD, out,
                                     T_LEN, DM, KD, nullptr, nullptr);
}